// round 9
// baseline (speedup 1.0000x reference)
#include <cuda_runtime.h>
#include <math.h>

// bs=4096, nt=2048. Output depends only on the LAST batch row:
//   S    = sum_j [ (y-mu)^2/sigma + log(sigma) ]   over row (bs-1)
//   loss = 0.5 * (S + nt*log(2*pi)) / (nt*bs)
// Single-block latency-floor reduction over 24 KiB.
// R8: common-denominator fusion. All 4 quadratic terms share one divide:
//   P = s0 s1 s2 s3  (also feeds the fused log)
//   num = (d0^2 s1 + d1^2 s0) * s2 s3 + (d2^2 s3 + d3^2 s2) * s0 s1
//   acc = num * rcp(P) + log(P)
// => 2 MUFU per thread (RCP + LG2) instead of 5. P in [1e-4, 1.5]: safe.

#define BS 4096
#define NT 2048
#define LOG_2PI 1.8378770664093453f

__global__ __launch_bounds__(512, 1)
void criterion_lastrow_kernel(const float4* __restrict__ mu,
                              const float4* __restrict__ sigma,
                              const float4* __restrict__ target_y,
                              float* __restrict__ out) {
    const int tid = threadIdx.x;   // 0..511, each handles 4 floats

    // 3 coalesced LDG.128, issued at kernel entry (offset folded on host).
    const float4 m = mu[tid];
    const float4 s = sigma[tid];
    const float4 y = target_y[tid];

    const float d0 = y.x - m.x;
    const float d1 = y.y - m.y;
    const float d2 = y.z - m.z;
    const float d3 = y.w - m.w;

    const float p01 = s.x * s.y;
    const float p23 = s.z * s.w;
    const float P   = p01 * p23;

    const float num = (d0 * d0 * s.y + d1 * d1 * s.x) * p23
                    + (d2 * d2 * s.w + d3 * d3 * s.z) * p01;

    // One MUFU.RCP + one MUFU.LG2 per thread.
    float acc = num * __frcp_rn(P) + __logf(P);

    // Warp reduction
    #pragma unroll
    for (int off = 16; off > 0; off >>= 1)
        acc += __shfl_xor_sync(0xFFFFFFFFu, acc, off);

    __shared__ float warp_sums[16];
    const int wid = tid >> 5;
    const int lid = tid & 31;
    if (lid == 0) warp_sums[wid] = acc;
    __syncthreads();

    if (wid == 0) {
        float v = (lid < 16) ? warp_sums[lid] : 0.0f;
        #pragma unroll
        for (int off = 8; off > 0; off >>= 1)
            v += __shfl_xor_sync(0xFFFFFFFFu, v, off);
        if (lid == 0) {
            const float scale = 0.5f / ((float)NT * (float)BS);
            out[0] = (v + (float)NT * LOG_2PI) * scale;
        }
    }
}

extern "C" void kernel_launch(void* const* d_in, const int* in_sizes, int n_in,
                              void* d_out, int out_size) {
    const long long base = (long long)(BS - 1) * NT;  // fold offset on host
    const float4* mu       = (const float4*)((const float*)d_in[0] + base);
    const float4* sigma    = (const float4*)((const float*)d_in[1] + base);
    const float4* target_y = (const float4*)((const float*)d_in[2] + base);
    criterion_lastrow_kernel<<<1, 512>>>(mu, sigma, target_y, (float*)d_out);
}

// round 10
// speedup vs baseline: 1.4345x; 1.4345x over previous
#include <cuda_runtime.h>
#include <math.h>

// bs=4096, nt=2048. Output depends only on the LAST batch row:
//   S    = sum_j [ (y-mu)^2/sigma + log(sigma) ]   over row (bs-1)
//   loss = 0.5 * (S + nt*log(2*pi)) / (nt*bs)
// Single-block latency-floor reduction over 24 KiB (L2-resident across
// graph replays -> ~250cy loads, fully MLP-hidden).
// R9: R8 body (common-denominator fusion: 1 RCP + 1 LG2 per thread) with a
//     balanced fma tree for num (depth 3) and MUFUs hoisted to depend only
//     on sigma so they issue before the diff chain completes.

#define BS 4096
#define NT 2048
#define LOG_2PI 1.8378770664093453f

__global__ __launch_bounds__(512, 1)
void criterion_lastrow_kernel(const float4* __restrict__ mu,
                              const float4* __restrict__ sigma,
                              const float4* __restrict__ target_y,
                              float* __restrict__ out) {
    const int tid = threadIdx.x;   // 0..511, each handles 4 floats

    // 3 coalesced LDG.128, issued at kernel entry (offset folded on host).
    const float4 s = sigma[tid];     // load sigma first: MUFUs depend only on it
    const float4 m = mu[tid];
    const float4 y = target_y[tid];

    // sigma-only products -> both MUFUs can issue as soon as s lands.
    const float p01 = s.x * s.y;
    const float p23 = s.z * s.w;
    const float P   = p01 * p23;
    const float r   = __frcp_rn(P);   // MUFU.RCP
    const float lg  = __logf(P);      // MUFU.LG2 (+1 FMUL)

    const float d0 = y.x - m.x;
    const float d1 = y.y - m.y;
    const float d2 = y.z - m.z;
    const float d3 = y.w - m.w;

    // num = (d0^2 s1 + d1^2 s0) * p23 + (d2^2 s3 + d3^2 s2) * p01, balanced.
    const float t01 = fmaf(d0 * d0, s.y, d1 * d1 * s.x);
    const float t23 = fmaf(d2 * d2, s.w, d3 * d3 * s.z);
    const float num = fmaf(t01, p23, t23 * p01);

    float acc = fmaf(num, r, lg);

    // Warp reduction
    #pragma unroll
    for (int off = 16; off > 0; off >>= 1)
        acc += __shfl_xor_sync(0xFFFFFFFFu, acc, off);

    __shared__ float warp_sums[16];
    const int wid = tid >> 5;
    const int lid = tid & 31;
    if (lid == 0) warp_sums[wid] = acc;
    __syncthreads();

    if (wid == 0) {
        float v = (lid < 16) ? warp_sums[lid] : 0.0f;
        #pragma unroll
        for (int off = 8; off > 0; off >>= 1)
            v += __shfl_xor_sync(0xFFFFFFFFu, v, off);
        if (lid == 0) {
            const float scale = 0.5f / ((float)NT * (float)BS);
            out[0] = (v + (float)NT * LOG_2PI) * scale;
        }
    }
}

extern "C" void kernel_launch(void* const* d_in, const int* in_sizes, int n_in,
                              void* d_out, int out_size) {
    const long long base = (long long)(BS - 1) * NT;  // fold offset on host
    const float4* mu       = (const float4*)((const float*)d_in[0] + base);
    const float4* sigma    = (const float4*)((const float*)d_in[1] + base);
    const float4* target_y = (const float4*)((const float*)d_in[2] + base);
    criterion_lastrow_kernel<<<1, 512>>>(mu, sigma, target_y, (float*)d_out);
}